// round 1
// baseline (speedup 1.0000x reference)
#include <cuda_runtime.h>

#define NN   100000
#define EE   800000
#define DIN_ 256
#define HH   128
#define EPSF 1e-5f

// ---------------- static device scratch (no allocs allowed) ----------------
__device__ float g_t[(size_t)NN * HH];      // GEMM output (pre-aggregation)
__device__ float g_agg[(size_t)NN * HH];    // aggregated output (pre-BN)
__device__ int   g_deg[NN];
__device__ int   g_rowptr[NN + 1];
__device__ int   g_cursor[NN];
__device__ int   g_col[EE];
__device__ float g_dis[NN];
__device__ float g_sum[HH];
__device__ float g_sumsq[HH];
__device__ float g_mu[HH];
__device__ float g_scale[HH];
__device__ float g_beta[HH];

// ---------------- graph preprocessing ----------------
__global__ void zero_deg_kernel() {
    int i = blockIdx.x * 256 + threadIdx.x;
    if (i < NN) g_deg[i] = 0;
}

__global__ void count_kernel(const int* __restrict__ dst) {
    int e = blockIdx.x * 256 + threadIdx.x;
    if (e < EE) atomicAdd(&g_deg[dst[e]], 1);
}

// single-block exclusive scan of g_deg -> g_rowptr / g_cursor, plus dis = rsqrt(deg+1)
__global__ void scan_kernel() {
    __shared__ int warp_sums[32];
    __shared__ int s_carry;
    if (threadIdx.x == 0) s_carry = 0;
    __syncthreads();
    int lane = threadIdx.x & 31, wid = threadIdx.x >> 5;
    for (int base = 0; base < NN; base += 1024) {
        int i = base + (int)threadIdx.x;
        int v = (i < NN) ? g_deg[i] : 0;
        // inclusive warp scan
        int x = v;
        #pragma unroll
        for (int o = 1; o < 32; o <<= 1) {
            int y = __shfl_up_sync(0xFFFFFFFFu, x, o);
            if (lane >= o) x += y;
        }
        if (lane == 31) warp_sums[wid] = x;
        __syncthreads();
        if (wid == 0) {
            int ws = warp_sums[lane];
            #pragma unroll
            for (int o = 1; o < 32; o <<= 1) {
                int y = __shfl_up_sync(0xFFFFFFFFu, ws, o);
                if (lane >= o) ws += y;
            }
            warp_sums[lane] = ws;
        }
        __syncthreads();
        int incl = x + (wid ? warp_sums[wid - 1] : 0) + s_carry;
        int excl = incl - v;
        if (i < NN) {
            g_rowptr[i] = excl;
            g_cursor[i] = excl;
            g_dis[i]    = rsqrtf((float)(v + 1));
        }
        __syncthreads();                 // everyone has consumed old s_carry
        if (threadIdx.x == 1023) s_carry = incl;
        __syncthreads();
    }
    if (threadIdx.x == 0) g_rowptr[NN] = s_carry;
}

__global__ void fill_kernel(const int* __restrict__ src, const int* __restrict__ dst) {
    int e = blockIdx.x * 256 + threadIdx.x;
    if (e < EE) {
        int d = dst[e];
        int p = atomicAdd(&g_cursor[d], 1);
        g_col[p] = src[e];
    }
}

// ---------------- fp32 tiled GEMM: g_t = A @ W  (A: NN x K, W: K x 128) ----
// BN=true: A is g_agg with fused relu((a-mu)*scale+beta) applied on load.
template <int K, bool BN>
__global__ void __launch_bounds__(256) gemm_kernel(const float* __restrict__ Ain,
                                                   const float* __restrict__ W) {
    __shared__ float As[16][128];
    __shared__ float Bs[16][128];
    const float* A = BN ? (const float*)g_agg : Ain;

    int tid = threadIdx.x;
    int tx = tid & 15;    // output col group (8 cols)
    int ty = tid >> 4;    // output row group (8 rows)
    int row0 = blockIdx.x * 128;

    float acc[8][8];
    #pragma unroll
    for (int i = 0; i < 8; i++)
        #pragma unroll
        for (int j = 0; j < 8; j++) acc[i][j] = 0.f;

    for (int kk = 0; kk < K; kk += 16) {
        // load A tile (128 rows x 16 k): 512 float4
        #pragma unroll
        for (int it = 0; it < 2; it++) {
            int idx = tid + 256 * it;
            int r  = idx >> 2;
            int k4 = idx & 3;
            int grow = row0 + r;
            float4 v = make_float4(0.f, 0.f, 0.f, 0.f);
            if (grow < NN) v = *(const float4*)&A[(size_t)grow * K + kk + k4 * 4];
            if (BN) {
                int c = kk + k4 * 4;
                v.x = fmaxf(0.f, fmaf(v.x - g_mu[c + 0], g_scale[c + 0], g_beta[c + 0]));
                v.y = fmaxf(0.f, fmaf(v.y - g_mu[c + 1], g_scale[c + 1], g_beta[c + 1]));
                v.z = fmaxf(0.f, fmaf(v.z - g_mu[c + 2], g_scale[c + 2], g_beta[c + 2]));
                v.w = fmaxf(0.f, fmaf(v.w - g_mu[c + 3], g_scale[c + 3], g_beta[c + 3]));
            }
            As[k4 * 4 + 0][r] = v.x;
            As[k4 * 4 + 1][r] = v.y;
            As[k4 * 4 + 2][r] = v.z;
            As[k4 * 4 + 3][r] = v.w;
        }
        // load B tile (16 k x 128 cols): 512 float4
        #pragma unroll
        for (int it = 0; it < 2; it++) {
            int idx = tid + 256 * it;
            int kr = idx >> 5;
            int c4 = idx & 31;
            *(float4*)&Bs[kr][c4 * 4] = *(const float4*)&W[(size_t)(kk + kr) * 128 + c4 * 4];
        }
        __syncthreads();
        #pragma unroll
        for (int k = 0; k < 16; k++) {
            float a[8], b[8];
            #pragma unroll
            for (int i = 0; i < 8; i++) a[i] = As[k][ty * 8 + i];
            #pragma unroll
            for (int j = 0; j < 8; j++) b[j] = Bs[k][tx * 8 + j];
            #pragma unroll
            for (int i = 0; i < 8; i++)
                #pragma unroll
                for (int j = 0; j < 8; j++) acc[i][j] = fmaf(a[i], b[j], acc[i][j]);
        }
        __syncthreads();
    }
    // store
    #pragma unroll
    for (int i = 0; i < 8; i++) {
        int row = row0 + ty * 8 + i;
        if (row < NN) {
            float4 v0 = make_float4(acc[i][0], acc[i][1], acc[i][2], acc[i][3]);
            float4 v1 = make_float4(acc[i][4], acc[i][5], acc[i][6], acc[i][7]);
            *(float4*)&g_t[(size_t)row * HH + tx * 8 + 0] = v0;
            *(float4*)&g_t[(size_t)row * HH + tx * 8 + 4] = v1;
        }
    }
}

// ---------------- aggregation: g_agg = Dis * (A_csr @ (dis .* g_t)) + self + b
__global__ void __launch_bounds__(256) agg_kernel(const float* __restrict__ bias) {
    int v    = (blockIdx.x * 256 + threadIdx.x) >> 5;
    int lane = threadIdx.x & 31;
    if (v >= NN) return;
    int beg = g_rowptr[v], end = g_rowptr[v + 1];
    const float4* t4 = (const float4*)g_t;

    float ax = 0.f, ay = 0.f, az = 0.f, aw = 0.f;
    int e = beg;
    int s_next = (e < end) ? __ldg(&g_col[e]) : 0;
    while (e < end) {
        int s = s_next;
        ++e;
        if (e < end) s_next = __ldg(&g_col[e]);
        float c  = __ldg(&g_dis[s]);
        float4 t = __ldg(&t4[(size_t)s * 32 + lane]);
        ax = fmaf(c, t.x, ax);
        ay = fmaf(c, t.y, ay);
        az = fmaf(c, t.z, az);
        aw = fmaf(c, t.w, aw);
    }
    float  dv = g_dis[v];
    float  d2 = dv * dv;
    float4 sv = t4[(size_t)v * 32 + lane];
    float4 bb = ((const float4*)bias)[lane];
    float4 o;
    o.x = fmaf(dv, ax, fmaf(d2, sv.x, bb.x));
    o.y = fmaf(dv, ay, fmaf(d2, sv.y, bb.y));
    o.z = fmaf(dv, az, fmaf(d2, sv.z, bb.z));
    o.w = fmaf(dv, aw, fmaf(d2, sv.w, bb.w));
    ((float4*)g_agg)[(size_t)v * 32 + lane] = o;
}

// ---------------- BatchNorm statistics ----------------
__global__ void zero_stats_kernel() {
    int c = threadIdx.x;
    g_sum[c] = 0.f;
    g_sumsq[c] = 0.f;
}

__global__ void bnstats_kernel() {
    int c = threadIdx.x;  // 0..127
    float s = 0.f, s2 = 0.f;
    for (int r = blockIdx.x; r < NN; r += gridDim.x) {
        float v = g_agg[(size_t)r * HH + c];
        s += v;
        s2 = fmaf(v, v, s2);
    }
    atomicAdd(&g_sum[c], s);
    atomicAdd(&g_sumsq[c], s2);
}

__global__ void bnfinal_kernel(const float* __restrict__ g, const float* __restrict__ be) {
    int c = threadIdx.x;
    float mu  = g_sum[c] * (1.0f / (float)NN);
    float var = g_sumsq[c] * (1.0f / (float)NN) - mu * mu;
    g_mu[c]    = mu;
    g_scale[c] = g[c] * rsqrtf(var + EPSF);
    g_beta[c]  = be[c];
}

// ---------------- final projection: out = relu(bn(agg)) @ Wf + bf ----------
__global__ void __launch_bounds__(256) final_kernel(const float* __restrict__ Wf,
                                                    const float* __restrict__ bf,
                                                    float* __restrict__ out) {
    int v    = (blockIdx.x * 256 + threadIdx.x) >> 5;
    int lane = threadIdx.x & 31;
    if (v >= NN) return;
    float4 h  = ((const float4*)g_agg)[(size_t)v * 32 + lane];
    float4 mu = ((const float4*)g_mu)[lane];
    float4 sc = ((const float4*)g_scale)[lane];
    float4 be = ((const float4*)g_beta)[lane];
    float4 w  = ((const float4*)Wf)[lane];
    float r = fmaxf(0.f, fmaf(h.x - mu.x, sc.x, be.x)) * w.x
            + fmaxf(0.f, fmaf(h.y - mu.y, sc.y, be.y)) * w.y
            + fmaxf(0.f, fmaf(h.z - mu.z, sc.z, be.z)) * w.z
            + fmaxf(0.f, fmaf(h.w - mu.w, sc.w, be.w)) * w.w;
    #pragma unroll
    for (int o = 16; o; o >>= 1) r += __shfl_down_sync(0xFFFFFFFFu, r, o);
    if (lane == 0) out[v] = r + bf[0];
}

// ---------------- launch ----------------
extern "C" void kernel_launch(void* const* d_in, const int* in_sizes, int n_in,
                              void* d_out, int out_size) {
    const float* x   = (const float*)d_in[0];
    const int*   src = (const int*)d_in[1];
    const int*   dst = (const int*)d_in[2];
    const float* W1  = (const float*)d_in[3];
    const float* b1  = (const float*)d_in[4];
    const float* g1  = (const float*)d_in[5];
    const float* be1 = (const float*)d_in[6];
    const float* W2  = (const float*)d_in[7];
    const float* b2  = (const float*)d_in[8];
    const float* g2  = (const float*)d_in[9];
    const float* be2 = (const float*)d_in[10];
    const float* W3  = (const float*)d_in[11];
    const float* b3  = (const float*)d_in[12];
    const float* g3  = (const float*)d_in[13];
    const float* be3 = (const float*)d_in[14];
    const float* Wf  = (const float*)d_in[15];
    const float* bf  = (const float*)d_in[16];
    float* out = (float*)d_out;

    const int EB = (EE + 255) / 256;          // 3125
    const int NB = (NN + 255) / 256;          // 391
    const int GEMM_BLOCKS = (NN + 127) / 128; // 782
    const int WARP_BLOCKS = (NN * 32 + 255) / 256; // 12500

    // CSR build + degree normalization (recomputed every call; deterministic structure)
    zero_deg_kernel<<<NB, 256>>>();
    count_kernel<<<EB, 256>>>(dst);
    scan_kernel<<<1, 1024>>>();
    fill_kernel<<<EB, 256>>>(src, dst);

    // layer 1
    gemm_kernel<DIN_, false><<<GEMM_BLOCKS, 256>>>(x, W1);
    agg_kernel<<<WARP_BLOCKS, 256>>>(b1);
    zero_stats_kernel<<<1, 128>>>();
    bnstats_kernel<<<1024, 128>>>();
    bnfinal_kernel<<<1, 128>>>(g1, be1);

    // layer 2 (BN+ReLU of layer 1 fused into A-load)
    gemm_kernel<HH, true><<<GEMM_BLOCKS, 256>>>(nullptr, W2);
    agg_kernel<<<WARP_BLOCKS, 256>>>(b2);
    zero_stats_kernel<<<1, 128>>>();
    bnstats_kernel<<<1024, 128>>>();
    bnfinal_kernel<<<1, 128>>>(g2, be2);

    // layer 3
    gemm_kernel<HH, true><<<GEMM_BLOCKS, 256>>>(nullptr, W3);
    agg_kernel<<<WARP_BLOCKS, 256>>>(b3);
    zero_stats_kernel<<<1, 128>>>();
    bnstats_kernel<<<1024, 128>>>();
    bnfinal_kernel<<<1, 128>>>(g3, be3);

    // final projection
    final_kernel<<<WARP_BLOCKS, 256>>>(Wf, bf, out);
}

// round 3
// speedup vs baseline: 1.6029x; 1.6029x over previous
#include <cuda_runtime.h>
#include <cuda_bf16.h>
#include <cstdint>

#define NN   100000
#define EE   800000
#define DIN_ 256
#define HH   128
#define EPSF 1e-5f

#if defined(__CUDA_ARCH__) && (defined(__CUDA_ARCH_FEAT_SM103_ALL) || defined(__CUDA_ARCH_FEAT_SM100_ALL) || defined(__CUDA_ARCH_SPECIFIC__))
#define TC_OK 1
#else
#define TC_OK 0
#endif

// ---------------- static device scratch ----------------
__device__ float g_t[(size_t)NN * HH];      // GEMM output, pre-scaled by dis[row]
__device__ float g_agg[(size_t)NN * HH];    // aggregated output (pre-BN)
__device__ int   g_deg[NN];
__device__ int   g_rowptr[NN + 1];
__device__ int   g_cursor[NN];
__device__ int   g_col[EE];
__device__ float g_dis[NN];
__device__ float g_sum[HH];
__device__ float g_sumsq[HH];
__device__ float g_mu[HH];
__device__ float g_scale[HH];
__device__ float g_beta[HH];

// dyn smem: stage s at s*65536: {Ahi:+0, Alo:+16384, Bhi:+32768, Blo:+49152}
// header at 131072: {tmem_ptr:+0, mbar0:+8, mbar1:+16}
#define GSM_HDR   131072
#define GSM_TOTAL (131072 + 64)

#if TC_OK
// ---------------- tcgen05 ptx helpers ----------------
__device__ __forceinline__ uint32_t smem_u32(const void* p) {
    uint32_t a;
    asm("{ .reg .u64 t; cvta.to.shared.u64 t, %1; cvt.u32.u64 %0, t; }" : "=r"(a) : "l"(p));
    return a;
}
__device__ __forceinline__ uint32_t elect1() {
    uint32_t r;
    asm volatile("{ .reg .pred p; elect.sync _|p, 0xFFFFFFFF; selp.b32 %0, 1, 0, p; }" : "=r"(r));
    return r;
}
__device__ __forceinline__ void tc_alloc(uint32_t smem_addr, uint32_t n) {
    asm volatile("tcgen05.alloc.cta_group::1.sync.aligned.shared::cta.b32 [%0], %1;"
                 :: "r"(smem_addr), "r"(n) : "memory");
}
__device__ __forceinline__ void tc_relinq() {
    asm volatile("tcgen05.relinquish_alloc_permit.cta_group::1.sync.aligned;");
}
__device__ __forceinline__ void tc_dealloc(uint32_t tmem, uint32_t n) {
    asm volatile("tcgen05.dealloc.cta_group::1.sync.aligned.b32 %0, %1;" :: "r"(tmem), "r"(n));
}
__device__ __forceinline__ void tc_commit(uint32_t mbar) {
    asm volatile("tcgen05.commit.cta_group::1.mbarrier::arrive::one.shared::cluster.b64 [%0];"
                 :: "r"(mbar) : "memory");
}
__device__ __forceinline__ void mbar_init(uint32_t a, uint32_t c) {
    asm volatile("mbarrier.init.shared.b64 [%0], %1;" :: "r"(a), "r"(c) : "memory");
}
__device__ __forceinline__ void mbar_wait(uint32_t a, uint32_t ph) {
    asm volatile(
        "{\n\t.reg .pred P;\n"
        "W%=:\n\t"
        "mbarrier.try_wait.parity.acquire.cta.shared::cta.b64 P, [%0], %1, 0x989680;\n\t"
        "@P bra.uni D%=;\n\t"
        "bra.uni W%=;\n"
        "D%=:\n\t}"
        :: "r"(a), "r"(ph) : "memory");
}
__device__ __forceinline__ void tc_wait_ld()  { asm volatile("tcgen05.wait::ld.sync.aligned;" ::: "memory"); }
__device__ __forceinline__ void tc_fence_after() { asm volatile("tcgen05.fence::after_thread_sync;" ::: "memory"); }
__device__ __forceinline__ void fence_async() { asm volatile("fence.proxy.async;" ::: "memory"); }

// SS-form bf16 MMA, cta_group::1, kind::f16 (proven on sm_103a in examples)
__device__ __forceinline__ void mma_bf16(uint32_t d, uint64_t a, uint64_t b, uint32_t id, uint32_t en) {
    asm volatile(
        "{\n\t.reg .pred p;\n\tsetp.ne.u32 p, %5, 0;\n\t"
        "tcgen05.mma.cta_group::1.kind::f16 [%0], %1, %2, %3, {%4, %4, %4, %4}, p;\n\t}"
        :: "r"(d), "l"(a), "l"(b), "r"(id), "r"(0u), "r"(en) : "memory");
}
__device__ __forceinline__ void ldtm_x32(uint32_t* r, uint32_t addr) {
    asm volatile(
        "tcgen05.ld.sync.aligned.32x32b.x32.b32 "
        "{%0, %1, %2, %3, %4, %5, %6, %7, %8, %9, %10, %11, %12, %13, %14, %15, "
        "%16, %17, %18, %19, %20, %21, %22, %23, %24, %25, %26, %27, %28, %29, %30, %31}, [%32];"
        : "=r"(r[0]), "=r"(r[1]), "=r"(r[2]), "=r"(r[3]), "=r"(r[4]), "=r"(r[5]), "=r"(r[6]), "=r"(r[7]),
          "=r"(r[8]), "=r"(r[9]), "=r"(r[10]), "=r"(r[11]), "=r"(r[12]), "=r"(r[13]), "=r"(r[14]), "=r"(r[15]),
          "=r"(r[16]), "=r"(r[17]), "=r"(r[18]), "=r"(r[19]), "=r"(r[20]), "=r"(r[21]), "=r"(r[22]), "=r"(r[23]),
          "=r"(r[24]), "=r"(r[25]), "=r"(r[26]), "=r"(r[27]), "=r"(r[28]), "=r"(r[29]), "=r"(r[30]), "=r"(r[31])
        : "r"(addr));
}
__device__ __forceinline__ uint32_t sw128(uint32_t o) { return o ^ ((o >> 3) & 0x70); }

// SMEM descriptor: SW128, version=1, SBO=64, LBO=1 (K-major, 128B rows)
__device__ __forceinline__ uint64_t smem_desc(uint32_t addr) {
    const uint64_t base = (2ull << 61) | (1ull << 46) | (64ull << 32) | (1ull << 16);
    return base | ((uint64_t)(addr >> 4) & 0x3FFF);
}
// idesc kind::f16: D=f32(1<<4), A=bf16(1<<7), B=bf16(1<<10), N=128(16<<17), M=128(8<<24)
#define IDESC_BF16 ((1u << 4) | (1u << 7) | (1u << 10) | (16u << 17) | (8u << 24))

// split 8 floats -> 4 packed bf16x2 hi + 4 packed bf16x2 lo
__device__ __forceinline__ void split8(const float* v, uint32_t* hi, uint32_t* lo) {
    #pragma unroll
    for (int j = 0; j < 4; j++) {
        float a = v[2 * j], b = v[2 * j + 1];
        __nv_bfloat16 ha = __float2bfloat16_rn(a);
        __nv_bfloat16 hb = __float2bfloat16_rn(b);
        float la = a - __bfloat162float(ha);
        float lb = b - __bfloat162float(hb);
        __nv_bfloat162 hh; hh.x = ha; hh.y = hb;
        __nv_bfloat162 ll; ll.x = __float2bfloat16_rn(la); ll.y = __float2bfloat16_rn(lb);
        hi[j] = *(uint32_t*)&hh;
        lo[j] = *(uint32_t*)&ll;
    }
}
#endif  // TC_OK

// ---------------- graph preprocessing ----------------
__global__ void zero_deg_kernel() {
    int i = blockIdx.x * 256 + threadIdx.x;
    if (i < NN) g_deg[i] = 0;
}

__global__ void count_kernel(const int* __restrict__ dst) {
    int e = blockIdx.x * 256 + threadIdx.x;
    if (e < EE) atomicAdd(&g_deg[dst[e]], 1);
}

__global__ void scan_kernel() {
    __shared__ int warp_sums[32];
    __shared__ int s_carry;
    if (threadIdx.x == 0) s_carry = 0;
    if (threadIdx.x < 128) { g_sum[threadIdx.x] = 0.f; g_sumsq[threadIdx.x] = 0.f; }
    __syncthreads();
    int lane = threadIdx.x & 31, wid = threadIdx.x >> 5;
    for (int base = 0; base < NN; base += 1024) {
        int i = base + (int)threadIdx.x;
        int v = (i < NN) ? g_deg[i] : 0;
        int x = v;
        #pragma unroll
        for (int o = 1; o < 32; o <<= 1) {
            int y = __shfl_up_sync(0xFFFFFFFFu, x, o);
            if (lane >= o) x += y;
        }
        if (lane == 31) warp_sums[wid] = x;
        __syncthreads();
        if (wid == 0) {
            int ws = warp_sums[lane];
            #pragma unroll
            for (int o = 1; o < 32; o <<= 1) {
                int y = __shfl_up_sync(0xFFFFFFFFu, ws, o);
                if (lane >= o) ws += y;
            }
            warp_sums[lane] = ws;
        }
        __syncthreads();
        int incl = x + (wid ? warp_sums[wid - 1] : 0) + s_carry;
        int excl = incl - v;
        if (i < NN) {
            g_rowptr[i] = excl;
            g_cursor[i] = excl;
            g_dis[i]    = rsqrtf((float)(v + 1));
        }
        __syncthreads();
        if (threadIdx.x == 1023) s_carry = incl;
        __syncthreads();
    }
    if (threadIdx.x == 0) g_rowptr[NN] = s_carry;
}

__global__ void fill_kernel(const int* __restrict__ src, const int* __restrict__ dst) {
    int e = blockIdx.x * 256 + threadIdx.x;
    if (e < EE) {
        int d = dst[e];
        int p = atomicAdd(&g_cursor[d], 1);
        g_col[p] = src[e];
    }
}

// ---------------- GEMM: g_t[row] = dis[row] * (A @ W)[row] ----------------
// A = Ain (K=256) or relu(bn(g_agg)) (K=128, BN fused on load)
template <int K, bool BN>
__global__ void __launch_bounds__(256, 1)
gemm_tc(const float* __restrict__ Ain, const float* __restrict__ W) {
    extern __shared__ char sm[];
    const float* A = BN ? (const float*)g_agg : Ain;
    int tid  = threadIdx.x;
    int row0 = blockIdx.x * 128;

#if TC_OK
    // ================= tcgen05 bf16 hi/lo compensated path =================
    uint32_t sb  = smem_u32(sm);
    int wid  = tid >> 5;
    int lane = tid & 31;
    constexpr int NC = K / 64;

    if (wid == 0) { tc_alloc(sb + GSM_HDR, 128); tc_relinq(); }
    if (tid == 0) { mbar_init(sb + GSM_HDR + 8, 1); mbar_init(sb + GSM_HDR + 16, 1); }
    __syncthreads();
    uint32_t tmem;
    asm volatile("ld.shared.b32 %0, [%1];" : "=r"(tmem) : "r"(sb + GSM_HDR));
    uint32_t mb[2] = { sb + GSM_HDR + 8, sb + GSM_HDR + 16 };

    auto load_chunk = [&](int c, int st) {
        char* tile = sm + st * 65536;
        // A tile: 128 rows x 64 floats -> bf16 hi/lo, 128B rows, SW128
        {
            int r = tid >> 1, h = tid & 1;
            int grow = row0 + r;
            const float* ap = A + (size_t)grow * K + c * 64 + h * 32;
            #pragma unroll
            for (int i = 0; i < 4; i++) {
                float v[8];
                if (grow < NN) {
                    float4 p0 = *(const float4*)(ap + i * 8);
                    float4 p1 = *(const float4*)(ap + i * 8 + 4);
                    v[0] = p0.x; v[1] = p0.y; v[2] = p0.z; v[3] = p0.w;
                    v[4] = p1.x; v[5] = p1.y; v[6] = p1.z; v[7] = p1.w;
                } else {
                    #pragma unroll
                    for (int j = 0; j < 8; j++) v[j] = 0.f;
                }
                if (BN) {
                    int col = c * 64 + h * 32 + i * 8;
                    #pragma unroll
                    for (int j = 0; j < 8; j++)
                        v[j] = fmaxf(0.f, fmaf(v[j] - g_mu[col + j], g_scale[col + j], g_beta[col + j]));
                }
                uint32_t hi[4], lo[4];
                split8(v, hi, lo);
                uint32_t so = sw128((uint32_t)(r * 128 + h * 64 + i * 16));
                *(uint4*)(tile + so)         = make_uint4(hi[0], hi[1], hi[2], hi[3]);
                *(uint4*)(tile + 16384 + so) = make_uint4(lo[0], lo[1], lo[2], lo[3]);
            }
        }
        // B tile: Bs[n][k] = W[c*64+k][n], 128 n-rows x 64 k bf16 (128B rows)
        {
            #pragma unroll
            for (int i = 0; i < 4; i++) {
                int e  = tid + 256 * i;      // 0..1023
                int n  = e & 127;
                int kb = (e >> 7) * 8;       // 0,8,...,56
                float v[8];
                #pragma unroll
                for (int j = 0; j < 8; j++) v[j] = W[(size_t)(c * 64 + kb + j) * 128 + n];
                uint32_t hi[4], lo[4];
                split8(v, hi, lo);
                uint32_t so = sw128((uint32_t)(n * 128 + kb * 2));
                *(uint4*)(tile + 32768 + so) = make_uint4(hi[0], hi[1], hi[2], hi[3]);
                *(uint4*)(tile + 49152 + so) = make_uint4(lo[0], lo[1], lo[2], lo[3]);
            }
        }
    };

    // prologue
    load_chunk(0, 0);
    fence_async();
    __syncthreads();

    // mainloop: chunk c commits to mb[c&1]; stage reuse waits chunk c-1
    for (int c = 0; c < NC; c++) {
        int s = c & 1;
        if (wid == 0 && elect1()) {
            uint32_t st = sb + s * 65536;
            uint64_t ah = smem_desc(st);
            uint64_t al = smem_desc(st + 16384);
            uint64_t bh = smem_desc(st + 32768);
            uint64_t bl = smem_desc(st + 49152);
            #pragma unroll
            for (int k = 0; k < 4; k++) {     // 4 x K=16 per 64-chunk
                mma_bf16(tmem, ah + k * 2, bh + k * 2, IDESC_BF16, (c > 0) || (k > 0));
                mma_bf16(tmem, al + k * 2, bh + k * 2, IDESC_BF16, 1);
                mma_bf16(tmem, ah + k * 2, bl + k * 2, IDESC_BF16, 1);
            }
            tc_commit(mb[s]);
        }
        if (c + 1 < NC) {
            if (c >= 1) mbar_wait(mb[(c - 1) & 1], (uint32_t)(((c - 1) >> 1) & 1));
            load_chunk(c + 1, (c + 1) & 1);
            fence_async();
            __syncthreads();
        }
    }
    mbar_wait(mb[(NC - 1) & 1], (uint32_t)(((NC - 1) >> 1) & 1));
    tc_fence_after();

    // epilogue: TMEM -> regs (scale by dis) -> padded SMEM -> coalesced STG
    float* smemF = (float*)sm;     // 128 rows x 132 floats
    {
        int wsub = wid & 3;
        int half = (wid >> 2) * 64;
        int lr   = wsub * 32 + lane;
        int grow = row0 + lr;
        float dv = (grow < NN) ? g_dis[grow] : 0.f;
        #pragma unroll
        for (int pass = 0; pass < 2; pass++) {
            uint32_t regs[32];
            ldtm_x32(regs, tmem + half + pass * 32);
            tc_wait_ld();
            float* dstp = smemF + lr * 132 + half + pass * 32;
            #pragma unroll
            for (int q = 0; q < 8; q++) {
                float4 v;
                v.x = dv * __uint_as_float(regs[q * 4 + 0]);
                v.y = dv * __uint_as_float(regs[q * 4 + 1]);
                v.z = dv * __uint_as_float(regs[q * 4 + 2]);
                v.w = dv * __uint_as_float(regs[q * 4 + 3]);
                *(float4*)(dstp + q * 4) = v;
            }
        }
    }
    __syncthreads();
    #pragma unroll
    for (int i = 0; i < 16; i++) {
        int idx = tid + 256 * i;
        int r   = idx >> 5;
        int c4  = idx & 31;
        int grow = row0 + r;
        if (grow < NN)
            *(float4*)&g_t[(size_t)grow * HH + c4 * 4] = *(float4*)(smemF + r * 132 + c4 * 4);
    }
    __syncthreads();
    if (wid == 0) tc_dealloc(tmem, 128);

#else
    // ================= fallback: fp32 FFMA SIMT GEMM =================
    float* As = (float*)sm;             // [16][128]
    float* Bs = (float*)(sm + 8192);    // [16][128]
    int tx = tid & 15, ty = tid >> 4;

    float acc[8][8];
    #pragma unroll
    for (int i = 0; i < 8; i++)
        #pragma unroll
        for (int j = 0; j < 8; j++) acc[i][j] = 0.f;

    for (int kk = 0; kk < K; kk += 16) {
        #pragma unroll
        for (int it = 0; it < 2; it++) {
            int idx = tid + 256 * it;
            int r  = idx >> 2;
            int k4 = idx & 3;
            int grow = row0 + r;
            float4 v = make_float4(0.f, 0.f, 0.f, 0.f);
            if (grow < NN) v = *(const float4*)&A[(size_t)grow * K + kk + k4 * 4];
            if (BN) {
                int c = kk + k4 * 4;
                v.x = fmaxf(0.f, fmaf(v.x - g_mu[c + 0], g_scale[c + 0], g_beta[c + 0]));
                v.y = fmaxf(0.f, fmaf(v.y - g_mu[c + 1], g_scale[c + 1], g_beta[c + 1]));
                v.z = fmaxf(0.f, fmaf(v.z - g_mu[c + 2], g_scale[c + 2], g_beta[c + 2]));
                v.w = fmaxf(0.f, fmaf(v.w - g_mu[c + 3], g_scale[c + 3], g_beta[c + 3]));
            }
            As[(k4 * 4 + 0) * 128 + r] = v.x;
            As[(k4 * 4 + 1) * 128 + r] = v.y;
            As[(k4 * 4 + 2) * 128 + r] = v.z;
            As[(k4 * 4 + 3) * 128 + r] = v.w;
        }
        #pragma unroll
        for (int it = 0; it < 2; it++) {
            int idx = tid + 256 * it;
            int kr = idx >> 5;
            int c4 = idx & 31;
            *(float4*)&Bs[kr * 128 + c4 * 4] = *(const float4*)&W[(size_t)(kk + kr) * 128 + c4 * 4];
        }
        __syncthreads();
        #pragma unroll
        for (int k = 0; k < 16; k++) {
            float a[8], b[8];
            #pragma unroll
            for (int i = 0; i < 8; i++) a[i] = As[k * 128 + ty * 8 + i];
            #pragma unroll
            for (int j = 0; j < 8; j++) b[j] = Bs[k * 128 + tx * 8 + j];
            #pragma unroll
            for (int i = 0; i < 8; i++)
                #pragma unroll
                for (int j = 0; j < 8; j++) acc[i][j] = fmaf(a[i], b[j], acc[i][j]);
        }
        __syncthreads();
    }
    #pragma unroll
    for (int i = 0; i < 8; i++) {
        int row = row0 + ty * 8 + i;
        if (row < NN) {
            float dv = g_dis[row];
            float4 v0 = make_float4(dv * acc[i][0], dv * acc[i][1], dv * acc[i][2], dv * acc[i][3]);
            float4 v1 = make_float4(dv * acc[i][4], dv * acc[i][5], dv * acc[i][6], dv * acc[i][7]);
            *(float4*)&g_t[(size_t)row * HH + tx * 8 + 0] = v0;
            *(float4*)&g_t[(size_t)row * HH + tx * 8 + 4] = v1;
        }
    }
#endif
}

// ---------------- aggregation + fused BN stats (grid-stride) ----------------
// g_t holds t' = dis[row]*t.  o = dv*(sum_nbr t'[s] + t'[v]) + b
#define AGG_BLOCKS 1184
__global__ void __launch_bounds__(256) agg_kernel(const float* __restrict__ bias) {
    __shared__ float spart[8][128];   // per-warp o values (reused for sum then sq)
    int wid  = threadIdx.x >> 5;
    int lane = threadIdx.x & 31;
    int warp_global = blockIdx.x * 8 + wid;
    const int warps_total = AGG_BLOCKS * 8;
    const float4* t4 = (const float4*)g_t;
    float4 bb = ((const float4*)bias)[lane];

    float4 psum = make_float4(0.f, 0.f, 0.f, 0.f);
    float4 psq  = make_float4(0.f, 0.f, 0.f, 0.f);

    for (int v = warp_global; v < NN; v += warps_total) {
        int beg = g_rowptr[v], end = g_rowptr[v + 1];
        float ax = 0.f, ay = 0.f, az = 0.f, aw = 0.f;
        int e = beg;
        int s_next = (e < end) ? __ldg(&g_col[e]) : 0;
        while (e < end) {
            int s = s_next;
            ++e;
            if (e < end) s_next = __ldg(&g_col[e]);
            float4 t = __ldg(&t4[(size_t)s * 32 + lane]);
            ax += t.x; ay += t.y; az += t.z; aw += t.w;
        }
        float  dv = g_dis[v];
        float4 sv = t4[(size_t)v * 32 + lane];
        float4 o;
        o.x = fmaf(dv, ax + sv.x, bb.x);
        o.y = fmaf(dv, ay + sv.y, bb.y);
        o.z = fmaf(dv, az + sv.z, bb.z);
        o.w = fmaf(dv, aw + sv.w, bb.w);
        ((float4*)g_agg)[(size_t)v * 32 + lane] = o;
        psum.x += o.x; psum.y += o.y; psum.z += o.z; psum.w += o.w;
        psq.x  = fmaf(o.x, o.x, psq.x);
        psq.y  = fmaf(o.y, o.y, psq.y);
        psq.z  = fmaf(o.z, o.z, psq.z);
        psq.w  = fmaf(o.w, o.w, psq.w);
    }

    // block reduce (no atomics in smem): 8 warps x 128 cols
    *(float4*)&spart[wid][lane * 4] = psum;
    __syncthreads();
    if (threadIdx.x < 128) {
        float s = 0.f;
        #pragma unroll
        for (int w = 0; w < 8; w++) s += spart[w][threadIdx.x];
        atomicAdd(&g_sum[threadIdx.x], s);
    }
    __syncthreads();
    *(float4*)&spart[wid][lane * 4] = psq;
    __syncthreads();
    if (threadIdx.x < 128) {
        float s = 0.f;
        #pragma unroll
        for (int w = 0; w < 8; w++) s += spart[w][threadIdx.x];
        atomicAdd(&g_sumsq[threadIdx.x], s);
    }
}

__global__ void bnfinal_kernel(const float* __restrict__ g, const float* __restrict__ be) {
    int c = threadIdx.x;
    float mu  = g_sum[c] * (1.0f / (float)NN);
    float var = g_sumsq[c] * (1.0f / (float)NN) - mu * mu;
    g_mu[c]    = mu;
    g_scale[c] = g[c] * rsqrtf(var + EPSF);
    g_beta[c]  = be[c];
    g_sum[c]   = 0.f;
    g_sumsq[c] = 0.f;
}

// ---------------- final projection ----------------
__global__ void __launch_bounds__(256) final_kernel(const float* __restrict__ Wf,
                                                    const float* __restrict__ bf,
                                                    float* __restrict__ out) {
    int v    = (blockIdx.x * 256 + threadIdx.x) >> 5;
    int lane = threadIdx.x & 31;
    if (v >= NN) return;
    float4 h  = ((const float4*)g_agg)[(size_t)v * 32 + lane];
    float4 mu = ((const float4*)g_mu)[lane];
    float4 sc = ((const float4*)g_scale)[lane];
    float4 be = ((const float4*)g_beta)[lane];
    float4 w  = ((const float4*)Wf)[lane];
    float r = fmaxf(0.f, fmaf(h.x - mu.x, sc.x, be.x)) * w.x
            + fmaxf(0.f, fmaf(h.y - mu.y, sc.y, be.y)) * w.y
            + fmaxf(0.f, fmaf(h.z - mu.z, sc.z, be.z)) * w.z
            + fmaxf(0.f, fmaf(h.w - mu.w, sc.w, be.w)) * w.w;
    #pragma unroll
    for (int o = 16; o; o >>= 1) r += __shfl_down_sync(0xFFFFFFFFu, r, o);
    if (lane == 0) out[v] = r + bf[0];
}

// ---------------- launch ----------------
extern "C" void kernel_launch(void* const* d_in, const int* in_sizes, int n_in,
                              void* d_out, int out_size) {
    const float* x   = (const float*)d_in[0];
    const int*   src = (const int*)d_in[1];
    const int*   dst = (const int*)d_in[2];
    const float* W1  = (const float*)d_in[3];
    const float* b1  = (const float*)d_in[4];
    const float* g1  = (const float*)d_in[5];
    const float* be1 = (const float*)d_in[6];
    const float* W2  = (const float*)d_in[7];
    const float* b2  = (const float*)d_in[8];
    const float* g2  = (const float*)d_in[9];
    const float* be2 = (const float*)d_in[10];
    const float* W3  = (const float*)d_in[11];
    const float* b3  = (const float*)d_in[12];
    const float* g3  = (const float*)d_in[13];
    const float* be3 = (const float*)d_in[14];
    const float* Wf  = (const float*)d_in[15];
    const float* bf  = (const float*)d_in[16];
    float* out = (float*)d_out;

    cudaFuncSetAttribute(gemm_tc<DIN_, false>, cudaFuncAttributeMaxDynamicSharedMemorySize, GSM_TOTAL);
    cudaFuncSetAttribute(gemm_tc<HH,   true >, cudaFuncAttributeMaxDynamicSharedMemorySize, GSM_TOTAL);

    const int EB = (EE + 255) / 256;
    const int NB = (NN + 255) / 256;
    const int GB = (NN + 127) / 128;               // 782 GEMM tiles
    const int WB = (NN * 32 + 255) / 256;          // warp-per-node blocks (final)

    zero_deg_kernel<<<NB, 256>>>();
    count_kernel<<<EB, 256>>>(dst);
    scan_kernel<<<1, 1024>>>();
    fill_kernel<<<EB, 256>>>(src, dst);

    gemm_tc<DIN_, false><<<GB, 256, GSM_TOTAL>>>(x, W1);
    agg_kernel<<<AGG_BLOCKS, 256>>>(b1);
    bnfinal_kernel<<<1, 128>>>(g1, be1);

    gemm_tc<HH, true><<<GB, 256, GSM_TOTAL>>>(nullptr, W2);
    agg_kernel<<<AGG_BLOCKS, 256>>>(b2);
    bnfinal_kernel<<<1, 128>>>(g2, be2);

    gemm_tc<HH, true><<<GB, 256, GSM_TOTAL>>>(nullptr, W3);
    agg_kernel<<<AGG_BLOCKS, 256>>>(b3);
    bnfinal_kernel<<<1, 128>>>(g3, be3);

    final_kernel<<<WB, 256>>>(Wf, bf, out);
}

// round 4
// speedup vs baseline: 2.2878x; 1.4272x over previous
#include <cuda_runtime.h>
#include <cuda_bf16.h>
#include <cstdint>

#define NN   100000
#define EE   800000
#define DIN_ 256
#define HH   128
#define EPSF 1e-5f

#if defined(__CUDA_ARCH__) && (defined(__CUDA_ARCH_FEAT_SM103_ALL) || defined(__CUDA_ARCH_FEAT_SM100_ALL) || defined(__CUDA_ARCH_SPECIFIC__))
#define TC_OK 1
#else
#define TC_OK 0
#endif

// ---------------- static device scratch ----------------
__device__ float g_t[(size_t)NN * HH];      // GEMM output, pre-scaled by dis[row]
__device__ float g_agg[(size_t)NN * HH];    // aggregated output (pre-BN)
__device__ int   g_deg[NN];
__device__ int   g_rowptr[NN + 1];
__device__ int   g_cursor[NN];
__device__ int   g_col[EE];
__device__ float g_dis[NN];
__device__ float g_sum[HH];
__device__ float g_sumsq[HH];
__device__ float g_scale[HH];
__device__ float g_shift[HH];
__device__ int   g_bsum[400];
// packed W images: bf16 hi/lo, transposed, SW128-swizzled, 32KB per 64-K chunk
// L1: 4 chunks @0, L2: 2 chunks @131072, L3: 2 chunks @196608
__device__ __align__(16) unsigned char g_wpack[262144];

// dyn smem: single stage 64KB {Ahi:+0, Alo:+16384, Bhi:+32768, Blo:+49152}
// header at 65536: {tmem_ptr:+0, mbar:+8}
#define GSM_HDR   65536
#define GSM_TOTAL (65536 + 32)

#if TC_OK
// ---------------- tcgen05 ptx helpers ----------------
__device__ __forceinline__ uint32_t smem_u32(const void* p) {
    uint32_t a;
    asm("{ .reg .u64 t; cvta.to.shared.u64 t, %1; cvt.u32.u64 %0, t; }" : "=r"(a) : "l"(p));
    return a;
}
__device__ __forceinline__ uint32_t elect1() {
    uint32_t r;
    asm volatile("{ .reg .pred p; elect.sync _|p, 0xFFFFFFFF; selp.b32 %0, 1, 0, p; }" : "=r"(r));
    return r;
}
__device__ __forceinline__ void tc_alloc(uint32_t smem_addr, uint32_t n) {
    asm volatile("tcgen05.alloc.cta_group::1.sync.aligned.shared::cta.b32 [%0], %1;"
                 :: "r"(smem_addr), "r"(n) : "memory");
}
__device__ __forceinline__ void tc_relinq() {
    asm volatile("tcgen05.relinquish_alloc_permit.cta_group::1.sync.aligned;");
}
__device__ __forceinline__ void tc_dealloc(uint32_t tmem, uint32_t n) {
    asm volatile("tcgen05.dealloc.cta_group::1.sync.aligned.b32 %0, %1;" :: "r"(tmem), "r"(n));
}
__device__ __forceinline__ void tc_commit(uint32_t mbar) {
    asm volatile("tcgen05.commit.cta_group::1.mbarrier::arrive::one.shared::cluster.b64 [%0];"
                 :: "r"(mbar) : "memory");
}
__device__ __forceinline__ void mbar_init(uint32_t a, uint32_t c) {
    asm volatile("mbarrier.init.shared.b64 [%0], %1;" :: "r"(a), "r"(c) : "memory");
}
__device__ __forceinline__ void mbar_wait(uint32_t a, uint32_t ph) {
    asm volatile(
        "{\n\t.reg .pred P;\n"
        "W%=:\n\t"
        "mbarrier.try_wait.parity.acquire.cta.shared::cta.b64 P, [%0], %1, 0x989680;\n\t"
        "@P bra.uni D%=;\n\t"
        "bra.uni W%=;\n"
        "D%=:\n\t}"
        :: "r"(a), "r"(ph) : "memory");
}
__device__ __forceinline__ void tc_wait_ld()  { asm volatile("tcgen05.wait::ld.sync.aligned;" ::: "memory"); }
__device__ __forceinline__ void tc_fence_after() { asm volatile("tcgen05.fence::after_thread_sync;" ::: "memory"); }
__device__ __forceinline__ void fence_async() { asm volatile("fence.proxy.async;" ::: "memory"); }

__device__ __forceinline__ void mma_bf16(uint32_t d, uint64_t a, uint64_t b, uint32_t id, uint32_t en) {
    asm volatile(
        "{\n\t.reg .pred p;\n\tsetp.ne.u32 p, %5, 0;\n\t"
        "tcgen05.mma.cta_group::1.kind::f16 [%0], %1, %2, %3, {%4, %4, %4, %4}, p;\n\t}"
        :: "r"(d), "l"(a), "l"(b), "r"(id), "r"(0u), "r"(en) : "memory");
}
__device__ __forceinline__ void ldtm_x32(uint32_t* r, uint32_t addr) {
    asm volatile(
        "tcgen05.ld.sync.aligned.32x32b.x32.b32 "
        "{%0, %1, %2, %3, %4, %5, %6, %7, %8, %9, %10, %11, %12, %13, %14, %15, "
        "%16, %17, %18, %19, %20, %21, %22, %23, %24, %25, %26, %27, %28, %29, %30, %31}, [%32];"
        : "=r"(r[0]), "=r"(r[1]), "=r"(r[2]), "=r"(r[3]), "=r"(r[4]), "=r"(r[5]), "=r"(r[6]), "=r"(r[7]),
          "=r"(r[8]), "=r"(r[9]), "=r"(r[10]), "=r"(r[11]), "=r"(r[12]), "=r"(r[13]), "=r"(r[14]), "=r"(r[15]),
          "=r"(r[16]), "=r"(r[17]), "=r"(r[18]), "=r"(r[19]), "=r"(r[20]), "=r"(r[21]), "=r"(r[22]), "=r"(r[23]),
          "=r"(r[24]), "=r"(r[25]), "=r"(r[26]), "=r"(r[27]), "=r"(r[28]), "=r"(r[29]), "=r"(r[30]), "=r"(r[31])
        : "r"(addr));
}
__device__ __forceinline__ uint32_t sw128(uint32_t o) { return o ^ ((o >> 3) & 0x70); }

// SMEM descriptor: SW128, version=1, SBO=64, LBO=1 (K-major, 128B rows)
__device__ __forceinline__ uint64_t smem_desc(uint32_t addr) {
    const uint64_t base = (2ull << 61) | (1ull << 46) | (64ull << 32) | (1ull << 16);
    return base | ((uint64_t)(addr >> 4) & 0x3FFF);
}
// idesc kind::f16: D=f32(1<<4), A=bf16(1<<7), B=bf16(1<<10), N=128(16<<17), M=128(8<<24)
#define IDESC_BF16 ((1u << 4) | (1u << 7) | (1u << 10) | (16u << 17) | (8u << 24))

__device__ __forceinline__ void split8(const float* v, uint32_t* hi, uint32_t* lo) {
    #pragma unroll
    for (int j = 0; j < 4; j++) {
        float a = v[2 * j], b = v[2 * j + 1];
        __nv_bfloat16 ha = __float2bfloat16_rn(a);
        __nv_bfloat16 hb = __float2bfloat16_rn(b);
        float la = a - __bfloat162float(ha);
        float lb = b - __bfloat162float(hb);
        __nv_bfloat162 hh; hh.x = ha; hh.y = hb;
        __nv_bfloat162 ll; ll.x = __float2bfloat16_rn(la); ll.y = __float2bfloat16_rn(lb);
        hi[j] = *(uint32_t*)&hh;
        lo[j] = *(uint32_t*)&ll;
    }
}
#endif  // TC_OK

// ---------------- W pre-pack: bf16 hi/lo, transposed, swizzled ----------------
__global__ void prep_w(const float* __restrict__ W1, const float* __restrict__ W2,
                       const float* __restrict__ W3) {
#if TC_OK
    int b = blockIdx.x;
    const float* W;
    int c;
    unsigned char* out;
    if (b < 4)      { W = W1; c = b;     out = g_wpack + (size_t)b * 32768; }
    else if (b < 6) { W = W2; c = b - 4; out = g_wpack + 131072 + (size_t)(b - 4) * 32768; }
    else            { W = W3; c = b - 6; out = g_wpack + 196608 + (size_t)(b - 6) * 32768; }
    int tid = threadIdx.x;
    #pragma unroll
    for (int i = 0; i < 4; i++) {
        int e  = tid + 256 * i;
        int n  = e & 127;
        int kb = (e >> 7) * 8;
        float v[8];
        #pragma unroll
        for (int j = 0; j < 8; j++) v[j] = W[(size_t)(c * 64 + kb + j) * 128 + n];
        uint32_t hi[4], lo[4];
        split8(v, hi, lo);
        uint32_t so = sw128((uint32_t)(n * 128 + kb * 2));
        *(uint4*)(out + so)         = make_uint4(hi[0], hi[1], hi[2], hi[3]);
        *(uint4*)(out + 16384 + so) = make_uint4(lo[0], lo[1], lo[2], lo[3]);
    }
#endif
}

// ---------------- graph preprocessing ----------------
__global__ void zero_deg_kernel() {
    int i = blockIdx.x * 256 + threadIdx.x;
    if (i < NN) g_deg[i] = 0;
    if (blockIdx.x == 0) {
        if (threadIdx.x < HH)            g_sum[threadIdx.x] = 0.f;
        else if (threadIdx.x < 2 * HH)   g_sumsq[threadIdx.x - HH] = 0.f;
    }
}

__global__ void count_kernel(const int* __restrict__ dst) {
    int e = blockIdx.x * 256 + threadIdx.x;
    if (e < EE) atomicAdd(&g_deg[dst[e]], 1);
}

// phase 1: per-block exclusive scan of deg -> g_rowptr (local), block sums -> g_bsum
__global__ void scan1_kernel() {
    __shared__ int wsum[8];
    int idx  = blockIdx.x * 256 + threadIdx.x;
    int lane = threadIdx.x & 31, wid = threadIdx.x >> 5;
    int v = (idx < NN) ? g_deg[idx] : 0;
    int x = v;
    #pragma unroll
    for (int o = 1; o < 32; o <<= 1) {
        int y = __shfl_up_sync(0xFFFFFFFFu, x, o);
        if (lane >= o) x += y;
    }
    if (lane == 31) wsum[wid] = x;
    __syncthreads();
    if (threadIdx.x == 0) {
        int csum = 0;
        #pragma unroll
        for (int w = 0; w < 8; w++) { int t = wsum[w]; wsum[w] = csum; csum += t; }
        g_bsum[blockIdx.x] = csum;
    }
    __syncthreads();
    if (idx < NN) g_rowptr[idx] = x - v + wsum[wid];
}

// phase 2: exclusive scan of 391 block sums (1 warp), total -> g_bsum[391]
__global__ void scan2_kernel() {
    int lane = threadIdx.x;
    int carry = 0;
    for (int base = 0; base < 391; base += 32) {
        int i = base + lane;
        int v = (i < 391) ? g_bsum[i] : 0;
        int x = v;
        #pragma unroll
        for (int o = 1; o < 32; o <<= 1) {
            int y = __shfl_up_sync(0xFFFFFFFFu, x, o);
            if (lane >= o) x += y;
        }
        if (i < 391) g_bsum[i] = x - v + carry;
        carry += __shfl_sync(0xFFFFFFFFu, x, 31);
    }
    if (lane == 0) g_bsum[391] = carry;
}

// phase 3: apply offsets, build cursor/dis/rowptr[NN]
__global__ void scan3_kernel() {
    int idx = blockIdx.x * 256 + threadIdx.x;
    if (idx < NN) {
        int r = g_rowptr[idx] + g_bsum[blockIdx.x];
        g_rowptr[idx] = r;
        g_cursor[idx] = r;
        g_dis[idx]    = rsqrtf((float)(g_deg[idx] + 1));
    }
    if (idx == 0) g_rowptr[NN] = g_bsum[391];
}

__global__ void fill_kernel(const int* __restrict__ src, const int* __restrict__ dst) {
    int e = blockIdx.x * 256 + threadIdx.x;
    if (e < EE) {
        int d = dst[e];
        int p = atomicAdd(&g_cursor[d], 1);
        g_col[p] = src[e];
    }
}

// ---------------- GEMM: g_t[row] = dis[row] * (A @ W)[row] ----------------
template <int K, bool BN>
__global__ void __launch_bounds__(256, 2)
gemm_tc(const float* __restrict__ Ain, const float* __restrict__ W,
        const unsigned char* __restrict__ wpack) {
    extern __shared__ char sm[];
    const float* A = BN ? (const float*)g_agg : Ain;
    int tid  = threadIdx.x;
    int row0 = blockIdx.x * 128;

#if TC_OK
    uint32_t sb  = smem_u32(sm);
    int wid  = tid >> 5;
    int lane = tid & 31;
    constexpr int NC = K / 64;

    if (wid == 0) { tc_alloc(sb + GSM_HDR, 128); tc_relinq(); }
    if (tid == 0) mbar_init(sb + GSM_HDR + 8, 1);
    __syncthreads();
    uint32_t tmem;
    asm volatile("ld.shared.b32 %0, [%1];" : "=r"(tmem) : "r"(sb + GSM_HDR));
    uint32_t mb = sb + GSM_HDR + 8;

    auto load_chunk = [&](int c) {
        char* tile = sm;
        // A tile: 128 rows x 64 floats -> bf16 hi/lo, SW128
        {
            int r = tid >> 1, h = tid & 1;
            int grow = row0 + r;
            const float* ap = A + (size_t)grow * K + c * 64 + h * 32;
            #pragma unroll
            for (int i = 0; i < 4; i++) {
                float v[8];
                if (grow < NN) {
                    float4 p0 = *(const float4*)(ap + i * 8);
                    float4 p1 = *(const float4*)(ap + i * 8 + 4);
                    v[0] = p0.x; v[1] = p0.y; v[2] = p0.z; v[3] = p0.w;
                    v[4] = p1.x; v[5] = p1.y; v[6] = p1.z; v[7] = p1.w;
                } else {
                    #pragma unroll
                    for (int j = 0; j < 8; j++) v[j] = 0.f;
                }
                if (BN) {
                    int col = c * 64 + h * 32 + i * 8;
                    #pragma unroll
                    for (int j = 0; j < 8; j++)
                        v[j] = fmaxf(0.f, fmaf(v[j], g_scale[col + j], g_shift[col + j]));
                }
                uint32_t hi[4], lo[4];
                split8(v, hi, lo);
                uint32_t so = sw128((uint32_t)(r * 128 + h * 64 + i * 16));
                *(uint4*)(tile + so)         = make_uint4(hi[0], hi[1], hi[2], hi[3]);
                *(uint4*)(tile + 16384 + so) = make_uint4(lo[0], lo[1], lo[2], lo[3]);
            }
        }
        // B tile: straight 32KB copy from pre-packed swizzled image
        {
            const uint4* ws = (const uint4*)(wpack + (size_t)c * 32768);
            uint4* bd = (uint4*)(tile + 32768);
            #pragma unroll
            for (int i = 0; i < 8; i++) {
                int idx = tid + 256 * i;       // 0..2047
                bd[idx] = __ldg(&ws[idx]);
            }
        }
    };

    load_chunk(0);
    fence_async();
    __syncthreads();

    uint64_t ah = smem_desc(sb);
    uint64_t al = smem_desc(sb + 16384);
    uint64_t bh = smem_desc(sb + 32768);
    uint64_t bl = smem_desc(sb + 49152);

    for (int c = 0; c < NC; c++) {
        if (wid == 0 && elect1()) {
            #pragma unroll
            for (int k = 0; k < 4; k++) {       // 4 x K=16 per 64-chunk
                mma_bf16(tmem, ah + k * 2, bh + k * 2, IDESC_BF16, (c > 0) || (k > 0));
                mma_bf16(tmem, al + k * 2, bh + k * 2, IDESC_BF16, 1);
                mma_bf16(tmem, ah + k * 2, bl + k * 2, IDESC_BF16, 1);
            }
            tc_commit(mb);
        }
        if (c + 1 < NC) {
            mbar_wait(mb, (uint32_t)(c & 1));   // chunk c's MMAs done -> smem reusable
            load_chunk(c + 1);
            fence_async();
            __syncthreads();
        }
    }
    mbar_wait(mb, (uint32_t)((NC - 1) & 1));
    tc_fence_after();

    // epilogue: 2 passes of 64 cols; TMEM -> regs (scale) -> smem (stride 68) -> STG
    float* smemF = (float*)sm;
    int wsub  = wid & 3;
    int chalf = (wid >> 2) * 32;
    int lr    = wsub * 32 + lane;
    int growE = row0 + lr;
    float dv  = (growE < NN) ? g_dis[growE] : 0.f;
    #pragma unroll
    for (int p = 0; p < 2; p++) {
        uint32_t regs[32];
        ldtm_x32(regs, tmem + p * 64 + chalf);
        tc_wait_ld();
        float* dp = smemF + lr * 68 + chalf;
        #pragma unroll
        for (int q = 0; q < 8; q++) {
            float4 v;
            v.x = dv * __uint_as_float(regs[q * 4 + 0]);
            v.y = dv * __uint_as_float(regs[q * 4 + 1]);
            v.z = dv * __uint_as_float(regs[q * 4 + 2]);
            v.w = dv * __uint_as_float(regs[q * 4 + 3]);
            *(float4*)(dp + q * 4) = v;
        }
        __syncthreads();
        #pragma unroll
        for (int i = 0; i < 8; i++) {
            int idx = tid + 256 * i;            // 0..2047
            int r   = idx >> 4;
            int c4  = idx & 15;
            int gr  = row0 + r;
            if (gr < NN)
                *(float4*)&g_t[(size_t)gr * HH + p * 64 + c4 * 4] = *(float4*)(smemF + r * 68 + c4 * 4);
        }
        __syncthreads();
    }
    if (wid == 0) tc_dealloc(tmem, 128);

#else
    // fallback fp32 FFMA GEMM
    float* As = (float*)sm;
    float* Bs = (float*)(sm + 8192);
    int tx = tid & 15, ty = tid >> 4;
    float acc[8][8];
    #pragma unroll
    for (int i = 0; i < 8; i++)
        #pragma unroll
        for (int j = 0; j < 8; j++) acc[i][j] = 0.f;
    for (int kk = 0; kk < K; kk += 16) {
        #pragma unroll
        for (int it = 0; it < 2; it++) {
            int idx = tid + 256 * it;
            int r  = idx >> 2;
            int k4 = idx & 3;
            int grow = row0 + r;
            float4 v = make_float4(0.f, 0.f, 0.f, 0.f);
            if (grow < NN) v = *(const float4*)&A[(size_t)grow * K + kk + k4 * 4];
            if (BN) {
                int c = kk + k4 * 4;
                v.x = fmaxf(0.f, fmaf(v.x, g_scale[c + 0], g_shift[c + 0]));
                v.y = fmaxf(0.f, fmaf(v.y, g_scale[c + 1], g_shift[c + 1]));
                v.z = fmaxf(0.f, fmaf(v.z, g_scale[c + 2], g_shift[c + 2]));
                v.w = fmaxf(0.f, fmaf(v.w, g_scale[c + 3], g_shift[c + 3]));
            }
            As[(k4 * 4 + 0) * 128 + r] = v.x;
            As[(k4 * 4 + 1) * 128 + r] = v.y;
            As[(k4 * 4 + 2) * 128 + r] = v.z;
            As[(k4 * 4 + 3) * 128 + r] = v.w;
        }
        #pragma unroll
        for (int it = 0; it < 2; it++) {
            int idx = tid + 256 * it;
            int kr = idx >> 5;
            int c4 = idx & 31;
            *(float4*)&Bs[kr * 128 + c4 * 4] = *(const float4*)&W[(size_t)(kk + kr) * 128 + c4 * 4];
        }
        __syncthreads();
        #pragma unroll
        for (int k = 0; k < 16; k++) {
            float a[8], b[8];
            #pragma unroll
            for (int i = 0; i < 8; i++) a[i] = As[k * 128 + ty * 8 + i];
            #pragma unroll
            for (int j = 0; j < 8; j++) b[j] = Bs[k * 128 + tx * 8 + j];
            #pragma unroll
            for (int i = 0; i < 8; i++)
                #pragma unroll
                for (int j = 0; j < 8; j++) acc[i][j] = fmaf(a[i], b[j], acc[i][j]);
        }
        __syncthreads();
    }
    #pragma unroll
    for (int i = 0; i < 8; i++) {
        int row = row0 + ty * 8 + i;
        if (row < NN) {
            float dv = g_dis[row];
            float4 v0 = make_float4(dv * acc[i][0], dv * acc[i][1], dv * acc[i][2], dv * acc[i][3]);
            float4 v1 = make_float4(dv * acc[i][4], dv * acc[i][5], dv * acc[i][6], dv * acc[i][7]);
            *(float4*)&g_t[(size_t)row * HH + tx * 8 + 0] = v0;
            *(float4*)&g_t[(size_t)row * HH + tx * 8 + 4] = v1;
        }
    }
#endif
}

// ---------------- aggregation + fused BN stats (grid-stride, 2-deep pipeline) ----
#define AGG_BLOCKS 1184
__global__ void __launch_bounds__(256) agg_kernel(const float* __restrict__ bias) {
    __shared__ float spart[8][128];
    int wid  = threadIdx.x >> 5;
    int lane = threadIdx.x & 31;
    int warp_global = blockIdx.x * 8 + wid;
    const int warps_total = AGG_BLOCKS * 8;
    const float4* t4 = (const float4*)g_t;
    float4 bb = ((const float4*)bias)[lane];

    float4 psum = make_float4(0.f, 0.f, 0.f, 0.f);
    float4 psq  = make_float4(0.f, 0.f, 0.f, 0.f);

    for (int v = warp_global; v < NN; v += warps_total) {
        int beg = g_rowptr[v], end = g_rowptr[v + 1];
        float ax0 = 0.f, ay0 = 0.f, az0 = 0.f, aw0 = 0.f;
        float ax1 = 0.f, ay1 = 0.f, az1 = 0.f, aw1 = 0.f;
        int e  = beg;
        int sA = (beg     < end) ? __ldg(&g_col[beg])     : 0;
        int sB = (beg + 1 < end) ? __ldg(&g_col[beg + 1]) : 0;
        while (e + 2 <= end) {
            int sa = sA, sb = sB;
            sA = (e + 2 < end) ? __ldg(&g_col[e + 2]) : 0;
            sB = (e + 3 < end) ? __ldg(&g_col[e + 3]) : 0;
            float4 ta = __ldg(&t4[(size_t)sa * 32 + lane]);
            float4 tb = __ldg(&t4[(size_t)sb * 32 + lane]);
            ax0 += ta.x; ay0 += ta.y; az0 += ta.z; aw0 += ta.w;
            ax1 += tb.x; ay1 += tb.y; az1 += tb.z; aw1 += tb.w;
            e += 2;
        }
        if (e < end) {
            float4 ta = __ldg(&t4[(size_t)sA * 32 + lane]);
            ax0 += ta.x; ay0 += ta.y; az0 += ta.z; aw0 += ta.w;
        }
        float  dv = g_dis[v];
        float4 sv = t4[(size_t)v * 32 + lane];
        float4 o;
        o.x = fmaf(dv, ax0 + ax1 + sv.x, bb.x);
        o.y = fmaf(dv, ay0 + ay1 + sv.y, bb.y);
        o.z = fmaf(dv, az0 + az1 + sv.z, bb.z);
        o.w = fmaf(dv, aw0 + aw1 + sv.w, bb.w);
        ((float4*)g_agg)[(size_t)v * 32 + lane] = o;
        psum.x += o.x; psum.y += o.y; psum.z += o.z; psum.w += o.w;
        psq.x  = fmaf(o.x, o.x, psq.x);
        psq.y  = fmaf(o.y, o.y, psq.y);
        psq.z  = fmaf(o.z, o.z, psq.z);
        psq.w  = fmaf(o.w, o.w, psq.w);
    }

    *(float4*)&spart[wid][lane * 4] = psum;
    __syncthreads();
    if (threadIdx.x < 128) {
        float s = 0.f;
        #pragma unroll
        for (int w = 0; w < 8; w++) s += spart[w][threadIdx.x];
        atomicAdd(&g_sum[threadIdx.x], s);
    }
    __syncthreads();
    *(float4*)&spart[wid][lane * 4] = psq;
    __syncthreads();
    if (threadIdx.x < 128) {
        float s = 0.f;
        #pragma unroll
        for (int w = 0; w < 8; w++) s += spart[w][threadIdx.x];
        atomicAdd(&g_sumsq[threadIdx.x], s);
    }
}

__global__ void bnfinal_kernel(const float* __restrict__ g, const float* __restrict__ be) {
    int c = threadIdx.x;
    float mu  = g_sum[c] * (1.0f / (float)NN);
    float var = g_sumsq[c] * (1.0f / (float)NN) - mu * mu;
    float sc  = g[c] * rsqrtf(var + EPSF);
    g_scale[c] = sc;
    g_shift[c] = be[c] - mu * sc;
    g_sum[c]   = 0.f;
    g_sumsq[c] = 0.f;
}

// ---------------- final projection ----------------
__global__ void __launch_bounds__(256) final_kernel(const float* __restrict__ Wf,
                                                    const float* __restrict__ bf,
                                                    float* __restrict__ out) {
    int v    = (blockIdx.x * 256 + threadIdx.x) >> 5;
    int lane = threadIdx.x & 31;
    if (v >= NN) return;
    float4 h  = ((const float4*)g_agg)[(size_t)v * 32 + lane];
    float4 sc = ((const float4*)g_scale)[lane];
    float4 sh = ((const float4*)g_shift)[lane];
    float4 w  = ((const float4*)Wf)[lane];
    float r = fmaxf(0.f, fmaf(h.x, sc.x, sh.x)) * w.x
            + fmaxf(0.f, fmaf(h.y, sc.y, sh.y)) * w.y
            + fmaxf(0.f, fmaf(h.z, sc.z, sh.z)) * w.z
            + fmaxf(0.f, fmaf(h.w, sc.w, sh.w)) * w.w;
    #pragma unroll
    for (int o = 16; o; o >>= 1) r += __shfl_down_sync(0xFFFFFFFFu, r, o);
    if (lane == 0) out[v] = r + bf[0];
}

// ---------------- launch ----------------
extern "C" void kernel_launch(void* const* d_in, const int* in_sizes, int n_in,
                              void* d_out, int out_size) {
    const float* x   = (const float*)d_in[0];
    const int*   src = (const int*)d_in[1];
    const int*   dst = (const int*)d_in[2];
    const float* W1  = (const float*)d_in[3];
    const float* b1  = (const float*)d_in[4];
    const float* g1  = (const float*)d_in[5];
    const float* be1 = (const float*)d_in[6];
    const float* W2  = (const float*)d_in[7];
    const float* b2  = (const float*)d_in[8];
    const float* g2  = (const float*)d_in[9];
    const float* be2 = (const float*)d_in[10];
    const float* W3  = (const float*)d_in[11];
    const float* b3  = (const float*)d_in[12];
    const float* g3  = (const float*)d_in[13];
    const float* be3 = (const float*)d_in[14];
    const float* Wf  = (const float*)d_in[15];
    const float* bf  = (const float*)d_in[16];
    float* out = (float*)d_out;

    cudaFuncSetAttribute(gemm_tc<DIN_, false>, cudaFuncAttributeMaxDynamicSharedMemorySize, GSM_TOTAL);
    cudaFuncSetAttribute(gemm_tc<HH,   true >, cudaFuncAttributeMaxDynamicSharedMemorySize, GSM_TOTAL);

    unsigned char* wp;
    cudaGetSymbolAddress((void**)&wp, g_wpack);

    const int EB = (EE + 255) / 256;
    const int NB = (NN + 255) / 256;               // 391
    const int GB = (NN + 127) / 128;               // 782 GEMM tiles
    const int WB = (NN * 32 + 255) / 256;

    prep_w<<<8, 256>>>(W1, W2, W3);
    zero_deg_kernel<<<NB, 256>>>();
    count_kernel<<<EB, 256>>>(dst);
    scan1_kernel<<<NB, 256>>>();
    scan2_kernel<<<1, 32>>>();
    scan3_kernel<<<NB, 256>>>();
    fill_kernel<<<EB, 256>>>(src, dst);

    gemm_tc<DIN_, false><<<GB, 256, GSM_TOTAL>>>(x, W1, wp);
    agg_kernel<<<AGG_BLOCKS, 256>>>(b1);
    bnfinal_kernel<<<1, 128>>>(g1, be1);

    gemm_tc<HH, true><<<GB, 256, GSM_TOTAL>>>(nullptr, W2, wp + 131072);
    agg_kernel<<<AGG_BLOCKS, 256>>>(b2);
    bnfinal_kernel<<<1, 128>>>(g2, be2);

    gemm_tc<HH, true><<<GB, 256, GSM_TOTAL>>>(nullptr, W3, wp + 196608);
    agg_kernel<<<AGG_BLOCKS, 256>>>(b3);
    bnfinal_kernel<<<1, 128>>>(g3, be3);

    final_kernel<<<WB, 256>>>(Wf, bf, out);
}